// round 10
// baseline (speedup 1.0000x reference)
#include <cuda_runtime.h>
#include <cuda_bf16.h>
#include <mma.h>
#include <cstdint>

using namespace nvcuda;

#define NQ    16384
#define KP    32
#define C     512
#define HREF  512
#define HCONF 256
#define NSTEPS 3

#define MLPB  128      // mlp role blocks (grid-barrier cohort)
#define CONFB 160      // conf role blocks

// ---------------- scratch ----------------
__device__ float g_wmean[NSTEPS * KP * C];
__device__ float g_wsum [NSTEPS * KP];
__device__ float g_h    [NSTEPS * KP * HREF];
__device__ float g_hp   [KP * HCONF];
__device__ __nv_bfloat16 g_hq16[NQ * HCONF];          // 8 MB
__device__ float g_conf [KP];
__device__ __nv_bfloat16 g_qf16[NQ * C];              // 16 MB
__device__ __nv_bfloat16 g_wq16[C * HCONF];           // 256 KB
__device__ unsigned g_bar;
__device__ unsigned g_cdone;

// ================= K0: cvt (blocks 0..4159) + init (blocks 4160..4351) =================
__global__ void __launch_bounds__(256) k0_kernel(const float* __restrict__ proto,
                                                 const float* __restrict__ qf,
                                                 const float* __restrict__ Wc1,
                                                 float* __restrict__ out) {
    const int bid = blockIdx.x;
    if (bid < 4160) {
        const int idx = bid * 256 + threadIdx.x;
        const int NV_QF = NQ * C / 8;
        const float* src;
        __nv_bfloat16* dst;
        int v;
        if (idx < NV_QF) { src = qf; dst = g_qf16; v = idx; }
        else if (idx < NV_QF + C * HCONF / 8) {
            src = Wc1 + (size_t)C * HCONF; dst = g_wq16; v = idx - NV_QF;
        } else return;
        float4 a = *(const float4*)(src + (size_t)v * 8);
        float4 b = *(const float4*)(src + (size_t)v * 8 + 4);
        __nv_bfloat162 p0 = __floats2bfloat162_rn(a.x, a.y);
        __nv_bfloat162 p1 = __floats2bfloat162_rn(a.z, a.w);
        __nv_bfloat162 p2 = __floats2bfloat162_rn(b.x, b.y);
        __nv_bfloat162 p3 = __floats2bfloat162_rn(b.z, b.w);
        uint4 o;
        o.x = *(uint32_t*)&p0; o.y = *(uint32_t*)&p1;
        o.z = *(uint32_t*)&p2; o.w = *(uint32_t*)&p3;
        *(uint4*)(dst + (size_t)v * 8) = o;
    } else {
        const int idx = (bid - 4160) * 256 + threadIdx.x;
        if (idx < NSTEPS * KP * C)    g_wmean[idx] = 0.f;
        if (idx < NSTEPS * KP * HREF) g_h[idx]     = 0.f;
        if (idx < KP * HCONF)         g_hp[idx]    = 0.f;
        if (idx < NSTEPS * KP)        g_wsum[idx]  = 0.f;
        if (idx < KP)                 g_conf[idx]  = 0.f;
        if (idx == 0)                { g_bar = 0u; g_cdone = 0u; }
        if (idx < KP * C)             out[idx]     = proto[idx];
    }
}

// ================= K1a: wmean via WMMA bf16 (192 blocks, 86 KB smem) =================
#define SOFT_LD 40
#define K1A_SMEM 86016
__global__ void __launch_bounds__(256) k1a_kernel(const float* __restrict__ qd) {
    extern __shared__ char smraw[];
    __nv_bfloat16 (*s_soft)[SOFT_LD] = (__nv_bfloat16(*)[SOFT_LD])smraw;
    float (*s_out)[C] = (float(*)[C])(smraw + 256 * SOFT_LD * 2);

    const int step  = blockIdx.x >> 6;
    const int qbase = (blockIdx.x & 63) * 256;
    const int tid   = threadIdx.x;
    const int wid   = tid >> 5;

    {
        const float inv_t = 1.0f / (float)(step + 1);
        const float* row = qd + (size_t)(qbase + tid) * KP;
        float v[KP];
        float m = -1e30f;
#pragma unroll
        for (int i = 0; i < KP; i++) { v[i] = -row[i] * inv_t; m = fmaxf(m, v[i]); }
        float s = 0.f;
#pragma unroll
        for (int i = 0; i < KP; i++) { v[i] = __expf(v[i] - m); s += v[i]; }
        const float inv = 1.0f / s;
#pragma unroll
        for (int i = 0; i < KP; i++) s_soft[tid][i] = __float2bfloat16(v[i] * inv);
    }
    __syncthreads();

    if (tid < KP) {
        float s = 0.f;
        for (int q = 0; q < 256; q++) s += __bfloat162float(s_soft[q][tid]);
        atomicAdd(&g_wsum[step * KP + tid], s);
    }

    const int n0 = wid * 64;
    wmma::fragment<wmma::accumulator, 16, 16, 16, float> acc[2][4];
#pragma unroll
    for (int mi = 0; mi < 2; mi++)
#pragma unroll
        for (int ni = 0; ni < 4; ni++) wmma::fill_fragment(acc[mi][ni], 0.f);

    for (int kq = 0; kq < 256; kq += 16) {
        wmma::fragment<wmma::matrix_a, 16, 16, 16, __nv_bfloat16, wmma::col_major> af[2];
        wmma::fragment<wmma::matrix_b, 16, 16, 16, __nv_bfloat16, wmma::row_major> bf[4];
#pragma unroll
        for (int mi = 0; mi < 2; mi++)
            wmma::load_matrix_sync(af[mi], &s_soft[kq][mi * 16], SOFT_LD);
#pragma unroll
        for (int ni = 0; ni < 4; ni++)
            wmma::load_matrix_sync(bf[ni], g_qf16 + (size_t)(qbase + kq) * C + n0 + ni * 16, C);
#pragma unroll
        for (int mi = 0; mi < 2; mi++)
#pragma unroll
            for (int ni = 0; ni < 4; ni++)
                wmma::mma_sync(acc[mi][ni], af[mi], bf[ni], acc[mi][ni]);
    }

#pragma unroll
    for (int mi = 0; mi < 2; mi++)
#pragma unroll
        for (int ni = 0; ni < 4; ni++)
            wmma::store_matrix_sync(&s_out[mi * 16][n0 + ni * 16], acc[mi][ni], C,
                                    wmma::mem_row_major);
    __syncthreads();

    float* base = g_wmean + (size_t)step * KP * C;
    const float* src = &s_out[0][0];
#pragma unroll
    for (int i = 0; i < 64; i++) {
        int idx = tid + 256 * i;
        atomicAdd(base + idx, src[idx]);
    }
}

// ================= K1b: hq (blocks 0..511, 1 tile each) + hp (512..575) ================
#define HA_LD 72
#define HB_LD 72
#define STG_LD 66
#define K1B_SMEM 36864

__device__ __forceinline__ void hq_role(char* smraw, int t) {
    __nv_bfloat16 (*As)[HA_LD] = (__nv_bfloat16(*)[HA_LD])smraw;
    __nv_bfloat16 (*Bs)[HB_LD] = (__nv_bfloat16(*)[HB_LD])(smraw + 128 * HA_LD * 2);
    float (*stg)[STG_LD] = (float(*)[STG_LD])smraw;   // union: reused after K-loop
    const int tid = threadIdx.x;
    const int wid = tid >> 5;
    const int wm = wid >> 1;
    const int wn = wid & 1;
    const int m0 = (t & 127) * 128;
    const int n0 = (t >> 7) * 64;

    wmma::fragment<wmma::accumulator, 16, 16, 16, float> acc[2][2];
#pragma unroll
    for (int mi = 0; mi < 2; mi++)
#pragma unroll
        for (int ni = 0; ni < 2; ni++) wmma::fill_fragment(acc[mi][ni], 0.f);

    for (int kk = 0; kk < C; kk += 64) {
        __syncthreads();
#pragma unroll
        for (int i = 0; i < 4; i++) {
            int f = tid + 256 * i; int row = f >> 3; int c8 = f & 7;
            *(uint4*)&As[row][c8 * 8] =
                *(const uint4*)(g_qf16 + (size_t)(m0 + row) * C + kk + c8 * 8);
        }
#pragma unroll
        for (int i = 0; i < 2; i++) {
            int f = tid + 256 * i; int row = f >> 3; int c8 = f & 7;
            *(uint4*)&Bs[row][c8 * 8] =
                *(const uint4*)(g_wq16 + (size_t)(kk + row) * HCONF + n0 + c8 * 8);
        }
        __syncthreads();

#pragma unroll
        for (int s = 0; s < 4; s++) {
            wmma::fragment<wmma::matrix_a, 16, 16, 16, __nv_bfloat16, wmma::row_major> af[2];
            wmma::fragment<wmma::matrix_b, 16, 16, 16, __nv_bfloat16, wmma::row_major> bf[2];
#pragma unroll
            for (int mi = 0; mi < 2; mi++)
                wmma::load_matrix_sync(af[mi], &As[wm * 32 + mi * 16][s * 16], HA_LD);
#pragma unroll
            for (int ni = 0; ni < 2; ni++)
                wmma::load_matrix_sync(bf[ni], &Bs[s * 16][wn * 32 + ni * 16], HB_LD);
#pragma unroll
            for (int mi = 0; mi < 2; mi++)
#pragma unroll
                for (int ni = 0; ni < 2; ni++)
                    wmma::mma_sync(acc[mi][ni], af[mi], bf[ni], acc[mi][ni]);
        }
    }
    __syncthreads();   // K-loop done; safe to reuse As/Bs space for f32 staging
#pragma unroll
    for (int mi = 0; mi < 2; mi++)
#pragma unroll
        for (int ni = 0; ni < 2; ni++)
            wmma::store_matrix_sync(&stg[wm * 32 + mi * 16][wn * 32 + ni * 16],
                                    acc[mi][ni], STG_LD, wmma::mem_row_major);
    __syncthreads();
    // pack 128x64 f32 -> bf16 gmem
#pragma unroll
    for (int i = 0; i < 8; i++) {
        int f = tid + 256 * i;           // 0..2047, 4 f32 each
        int row = f >> 4; int c4 = (f & 15) * 4;
        float4 v = make_float4(stg[row][c4], stg[row][c4 + 1], stg[row][c4 + 2], stg[row][c4 + 3]);
        __nv_bfloat162 p0 = __floats2bfloat162_rn(v.x, v.y);
        __nv_bfloat162 p1 = __floats2bfloat162_rn(v.z, v.w);
        uint2 o; o.x = *(uint32_t*)&p0; o.y = *(uint32_t*)&p1;
        *(uint2*)(g_hq16 + (size_t)(m0 + row) * HCONF + n0 + c4) = o;
    }
}

__device__ __forceinline__ void hp_role(const float* __restrict__ proto,
                                        const float* __restrict__ Wc1, char* smraw, int b) {
    float (*a_s)[KP] = (float(*)[KP])smraw;
    float (*red)[KP][64] = (float(*)[KP][64])(smraw + 4096);
    const int tid = threadIdx.x;
    const int n  = tid & 63;
    const int kp = tid >> 6;
    const int ng = (b & 3) * 64 + n;
    const int cbase = (b >> 2) * 32;

#pragma unroll
    for (int r = 0; r < 4; r++) {
        int idx = tid + 256 * r;
        int ii = idx >> 5, k = idx & 31;
        a_s[ii][k] = proto[k * C + cbase + ii];
    }
    __syncthreads();

    float acc[KP];
#pragma unroll
    for (int k = 0; k < KP; k++) acc[k] = 0.f;

    const float* wptr = Wc1 + (size_t)(cbase + kp * 8) * HCONF + ng;
    float wv[8];
#pragma unroll
    for (int ii = 0; ii < 8; ii++) wv[ii] = wptr[(size_t)ii * HCONF];
#pragma unroll
    for (int ii = 0; ii < 8; ii++) {
        const float w = wv[ii];
        const float4* av = (const float4*)&a_s[kp * 8 + ii][0];
#pragma unroll
        for (int k4 = 0; k4 < 8; k4++) {
            float4 a4 = av[k4];
            acc[k4 * 4 + 0] = fmaf(a4.x, w, acc[k4 * 4 + 0]);
            acc[k4 * 4 + 1] = fmaf(a4.y, w, acc[k4 * 4 + 1]);
            acc[k4 * 4 + 2] = fmaf(a4.z, w, acc[k4 * 4 + 2]);
            acc[k4 * 4 + 3] = fmaf(a4.w, w, acc[k4 * 4 + 3]);
        }
    }
#pragma unroll
    for (int k = 0; k < KP; k++) red[kp][k][n] = acc[k];
    __syncthreads();
    if (tid < 64) {
#pragma unroll
        for (int k = 0; k < KP; k++) {
            float s = red[0][k][n] + red[1][k][n] + red[2][k][n] + red[3][k][n];
            atomicAdd(&g_hp[k * HCONF + ng], s);
        }
    }
}

__global__ void __launch_bounds__(256) k1b_kernel(const float* __restrict__ proto,
                                                  const float* __restrict__ Wc1) {
    extern __shared__ char dsm[];
    const int bid = blockIdx.x;
    if (bid < 512) hq_role(dsm, bid);
    else           hp_role(proto, Wc1, dsm, bid - 512);
}

// ================= K2: mlp (blocks 0..127) + conf (128..287) =================
__device__ __forceinline__ void grid_sync_at(unsigned want) {
    __threadfence();
    __syncthreads();
    if (threadIdx.x == 0) {
        atomicAdd(&g_bar, 1u);
        while (*(volatile unsigned*)&g_bar < want) __nanosleep(32);
    }
    __syncthreads();
}

__device__ __forceinline__ void mlp_role(float* __restrict__ refined,
        const float* __restrict__ W1, const float* __restrict__ W2,
        const float* __restrict__ b1, const float* __restrict__ b2, char* smraw) {
    float (*a_s)[KP] = (float(*)[KP])smraw;
    float (*red)[KP][64] = (float(*)[KP][64])(smraw + 8192);
    float (*s_winv)[KP] = (float(*)[KP])(smraw + 8192 + 32768);

    const int tid = threadIdx.x;
    const int n  = tid & 63;
    const int kp = tid >> 6;
    const int bx = blockIdx.x & 7;
    const int by = blockIdx.x >> 3;

    if (tid < NSTEPS * KP)
        s_winv[tid >> 5][tid & 31] = 1.0f / fmaxf(g_wsum[tid], 1e-6f);

    unsigned want = MLPB;

    for (int step = 0; step < NSTEPS; step++) {
        {
            const int ng = bx * 64 + n;
            const int kbase = by * 64;
            __syncthreads();
#pragma unroll
            for (int r = 0; r < 8; r++) {
                int idx = tid + 256 * r;
                int ii = idx >> 5, k = idx & 31;
                int i = kbase + ii;
                a_s[ii][k] = (i < C)
                    ? __ldcg(&refined[k * C + i])
                    : g_wmean[(size_t)(step * KP + k) * C + (i - C)] * s_winv[step][k];
            }
            __syncthreads();

            float acc[KP];
#pragma unroll
            for (int k = 0; k < KP; k++) acc[k] = 0.f;

            const float* wptr = W1 + (size_t)(kbase + kp * 16) * HREF + ng;
            float wv[16];
#pragma unroll
            for (int ii = 0; ii < 16; ii++) wv[ii] = wptr[(size_t)ii * HREF];
#pragma unroll
            for (int ii = 0; ii < 16; ii++) {
                const float w = wv[ii];
                const float4* av = (const float4*)&a_s[kp * 16 + ii][0];
#pragma unroll
                for (int k4 = 0; k4 < 8; k4++) {
                    float4 a4 = av[k4];
                    acc[k4 * 4 + 0] = fmaf(a4.x, w, acc[k4 * 4 + 0]);
                    acc[k4 * 4 + 1] = fmaf(a4.y, w, acc[k4 * 4 + 1]);
                    acc[k4 * 4 + 2] = fmaf(a4.z, w, acc[k4 * 4 + 2]);
                    acc[k4 * 4 + 3] = fmaf(a4.w, w, acc[k4 * 4 + 3]);
                }
            }
#pragma unroll
            for (int k = 0; k < KP; k++) red[kp][k][n] = acc[k];
            __syncthreads();
            if (tid < 64) {
#pragma unroll
                for (int k = 0; k < KP; k++) {
                    float s = red[0][k][n] + red[1][k][n] + red[2][k][n] + red[3][k][n];
                    atomicAdd(&g_h[(size_t)(step * KP + k) * HREF + ng], s);
                }
            }
        }
        grid_sync_at(want); want += MLPB;

        {
            const int cg = bx * 64 + n;
            const int jbase = by * 32;
#pragma unroll
            for (int r = 0; r < 4; r++) {
                int idx = tid + 256 * r;
                int ii = idx >> 5, k = idx & 31;
                int j = jbase + ii;
                a_s[ii][k] = fmaxf(__ldcg(&g_h[(size_t)(step * KP + k) * HREF + j]) + b1[j], 0.f);
            }
            __syncthreads();

            float acc[KP];
#pragma unroll
            for (int k = 0; k < KP; k++) acc[k] = 0.f;

            const float* wptr = W2 + (size_t)(jbase + kp * 8) * C + cg;
            float wv[8];
#pragma unroll
            for (int ii = 0; ii < 8; ii++) wv[ii] = wptr[(size_t)ii * C];
#pragma unroll
            for (int ii = 0; ii < 8; ii++) {
                const float w = wv[ii];
                const float4* av = (const float4*)&a_s[kp * 8 + ii][0];
#pragma unroll
                for (int k4 = 0; k4 < 8; k4++) {
                    float4 a4 = av[k4];
                    acc[k4 * 4 + 0] = fmaf(a4.x, w, acc[k4 * 4 + 0]);
                    acc[k4 * 4 + 1] = fmaf(a4.y, w, acc[k4 * 4 + 1]);
                    acc[k4 * 4 + 2] = fmaf(a4.z, w, acc[k4 * 4 + 2]);
                    acc[k4 * 4 + 3] = fmaf(a4.w, w, acc[k4 * 4 + 3]);
                }
            }
#pragma unroll
            for (int k = 0; k < KP; k++) red[kp][k][n] = acc[k];
            __syncthreads();
            if (tid < 64) {
                const float b2v = (by == 0) ? b2[cg] : 0.f;
#pragma unroll
                for (int k = 0; k < KP; k++) {
                    float s = red[0][k][n] + red[1][k][n] + red[2][k][n] + red[3][k][n];
                    atomicAdd(&refined[k * C + cg], 0.1f * (s + b2v));
                }
            }
        }
        if (step < NSTEPS - 1) { grid_sync_at(want); want += MLPB; }
    }
}

// conf with packed bf16x2 math; lane owns j = lane*8 .. lane*8+7
__device__ __forceinline__ void conf_role(const float* __restrict__ Wc2,
        const float* __restrict__ bc1, const float* __restrict__ bc2,
        float* __restrict__ out, char* smraw, int cb) {
    __nv_bfloat162 (*s_hp2)[HCONF / 2] = (__nv_bfloat162(*)[HCONF / 2])smraw;  // [32][128] 16 KB
    float (*s_part)[KP] = (float(*)[KP])(smraw + 16384);
    unsigned* s_last = (unsigned*)(smraw + 16384 + 1024);
    const int tid  = threadIdx.x;
    const int lane = tid & 31;
    const int warp = tid >> 5;

    // pack g_hp f32 -> bf16x2
    __nv_bfloat162* hpflat = &s_hp2[0][0];
#pragma unroll
    for (int r = 0; r < 16; r++) {
        int f = tid + 256 * r;                        // 0..4095 pair index
        float2 v = *(const float2*)&g_hp[2 * f];
        hpflat[f] = __floats2bfloat162_rn(v.x, v.y);
    }

    __nv_bfloat162 w2[4], bcr2[4];
#pragma unroll
    for (int t = 0; t < 4; t++) {
        int j = lane * 8 + 2 * t;
        w2[t]   = __floats2bfloat162_rn(Wc2[j], Wc2[j + 1]);
        bcr2[t] = __floats2bfloat162_rn(bc1[j], bc1[j + 1]);
    }
    const float bc2v = bc2[0];
    const __nv_bfloat162 zero2 = __floats2bfloat162_rn(0.f, 0.f);
    __syncthreads();

    float conf_acc = 0.f;
    const int nwarps = CONFB * 8;
    for (int q = cb * 8 + warp; q < NQ; q += nwarps) {
        uint4 hv = *(const uint4*)(g_hq16 + (size_t)q * HCONF + lane * 8);
        __nv_bfloat162 h2[4]; *(uint4*)h2 = hv;
        __nv_bfloat162 a2[4];
#pragma unroll
        for (int t = 0; t < 4; t++) a2[t] = __hadd2(h2[t], bcr2[t]);
#pragma unroll 4
        for (int k = 0; k < KP; k++) {
            uint4 hp4 = *(const uint4*)&s_hp2[k][lane * 4];
            __nv_bfloat162 p2[4]; *(uint4*)p2 = hp4;
            __nv_bfloat162 s2a = zero2, s2b = zero2;
            s2a = __hfma2(__hmax2(__hadd2(p2[0], a2[0]), zero2), w2[0], s2a);
            s2a = __hfma2(__hmax2(__hadd2(p2[1], a2[1]), zero2), w2[1], s2a);
            s2b = __hfma2(__hmax2(__hadd2(p2[2], a2[2]), zero2), w2[2], s2b);
            s2b = __hfma2(__hmax2(__hadd2(p2[3], a2[3]), zero2), w2[3], s2b);
            float2 fa = __bfloat1622float2(s2a);
            float2 fb = __bfloat1622float2(s2b);
            float s = (fa.x + fa.y) + (fb.x + fb.y);
            s += __shfl_xor_sync(0xffffffffu, s, 16);
            s += __shfl_xor_sync(0xffffffffu, s, 8);
            s += __shfl_xor_sync(0xffffffffu, s, 4);
            s += __shfl_xor_sync(0xffffffffu, s, 2);
            s += __shfl_xor_sync(0xffffffffu, s, 1);
            const float sig = 1.0f / (1.0f + __expf(-(s + bc2v)));
            if (k == lane) conf_acc += sig;
        }
    }
    s_part[warp][lane] = conf_acc;
    __syncthreads();
    if (tid < KP) {
        float t = 0.f;
#pragma unroll
        for (int w = 0; w < 8; w++) t += s_part[w][tid];
        atomicAdd(&g_conf[tid], t);
    }
    __threadfence();
    __syncthreads();
    if (tid == 0) *s_last = atomicAdd(&g_cdone, 1u);
    __syncthreads();
    if (*s_last == CONFB - 1) {
        if (tid < KP)
            out[KP * C + tid] = *((volatile float*)&g_conf[tid]) * (1.0f / (float)NQ);
    }
}

#define K2_SMEM 41472
__global__ void __launch_bounds__(256) k2_kernel(float* __restrict__ out,
        const float* __restrict__ W1, const float* __restrict__ W2,
        const float* __restrict__ b1, const float* __restrict__ b2,
        const float* __restrict__ Wc2, const float* __restrict__ bc1,
        const float* __restrict__ bc2) {
    extern __shared__ char dsm[];
    const int bid = blockIdx.x;
    if (bid < MLPB) mlp_role(out, W1, W2, b1, b2, dsm);
    else            conf_role(Wc2, bc1, bc2, out, dsm, bid - MLPB);
}

// ---------------- launch ----------------
extern "C" void kernel_launch(void* const* d_in, const int* in_sizes, int n_in,
                              void* d_out, int out_size) {
    const float* proto = (const float*)d_in[0];
    const float* qf    = (const float*)d_in[1];
    const float* qd    = (const float*)d_in[2];
    const float* W1    = (const float*)d_in[3];
    const float* b1    = (const float*)d_in[4];
    const float* W2    = (const float*)d_in[5];
    const float* b2    = (const float*)d_in[6];
    const float* Wc1   = (const float*)d_in[7];
    const float* bc1   = (const float*)d_in[8];
    const float* Wc2   = (const float*)d_in[9];
    const float* bc2   = (const float*)d_in[10];
    float* out = (float*)d_out;

    static int smem_set = 0;
    if (!smem_set) {
        cudaFuncSetAttribute(k1a_kernel, cudaFuncAttributeMaxDynamicSharedMemorySize, K1A_SMEM);
        cudaFuncSetAttribute(k1b_kernel, cudaFuncAttributeMaxDynamicSharedMemorySize, K1B_SMEM);
        cudaFuncSetAttribute(k2_kernel,  cudaFuncAttributeMaxDynamicSharedMemorySize, K2_SMEM);
        smem_set = 1;
    }

    k0_kernel<<<4352, 256>>>(proto, qf, Wc1, out);
    k1a_kernel<<<192, 256, K1A_SMEM>>>(qd);
    k1b_kernel<<<576, 256, K1B_SMEM>>>(proto, Wc1);
    k2_kernel<<<MLPB + CONFB, 256, K2_SMEM>>>(out, W1, W2, b1, b2, Wc2, bc1, bc2);
}

// round 11
// speedup vs baseline: 1.3372x; 1.3372x over previous
#include <cuda_runtime.h>
#include <cuda_bf16.h>
#include <mma.h>
#include <cstdint>

using namespace nvcuda;

#define NQ    16384
#define KP    32
#define C     512
#define HREF  512
#define HCONF 256
#define NSTEPS 3

#define MLPB  128      // mlp role blocks (grid-barrier cohort)
#define CONFB 160      // conf role blocks

// ---------------- scratch ----------------
__device__ float g_wmean[NSTEPS * KP * C];
__device__ float g_wsum [NSTEPS * KP];
__device__ float g_h    [NSTEPS * KP * HREF];
__device__ float g_hp   [KP * HCONF];
__device__ __nv_bfloat16 g_hq16[NQ * HCONF];          // 8 MB
__device__ float g_conf [KP];
__device__ __nv_bfloat16 g_qf16[NQ * C];              // 16 MB
__device__ __nv_bfloat16 g_wq16[C * HCONF];           // 256 KB
__device__ unsigned g_bar;
__device__ unsigned g_cdone;

// ================= K0: cvt (blocks 0..4159) + init (blocks 4160..4351) =================
__global__ void __launch_bounds__(256) k0_kernel(const float* __restrict__ proto,
                                                 const float* __restrict__ qf,
                                                 const float* __restrict__ Wc1,
                                                 float* __restrict__ out) {
    const int bid = blockIdx.x;
    if (bid < 4160) {
        const int idx = bid * 256 + threadIdx.x;
        const int NV_QF = NQ * C / 8;
        const float* src;
        __nv_bfloat16* dst;
        int v;
        if (idx < NV_QF) { src = qf; dst = g_qf16; v = idx; }
        else if (idx < NV_QF + C * HCONF / 8) {
            src = Wc1 + (size_t)C * HCONF; dst = g_wq16; v = idx - NV_QF;
        } else return;
        float4 a = *(const float4*)(src + (size_t)v * 8);
        float4 b = *(const float4*)(src + (size_t)v * 8 + 4);
        __nv_bfloat162 p0 = __floats2bfloat162_rn(a.x, a.y);
        __nv_bfloat162 p1 = __floats2bfloat162_rn(a.z, a.w);
        __nv_bfloat162 p2 = __floats2bfloat162_rn(b.x, b.y);
        __nv_bfloat162 p3 = __floats2bfloat162_rn(b.z, b.w);
        uint4 o;
        o.x = *(uint32_t*)&p0; o.y = *(uint32_t*)&p1;
        o.z = *(uint32_t*)&p2; o.w = *(uint32_t*)&p3;
        *(uint4*)(dst + (size_t)v * 8) = o;
    } else {
        const int idx = (bid - 4160) * 256 + threadIdx.x;
        if (idx < NSTEPS * KP * C)    g_wmean[idx] = 0.f;
        if (idx < NSTEPS * KP * HREF) g_h[idx]     = 0.f;
        if (idx < KP * HCONF)         g_hp[idx]    = 0.f;
        if (idx < NSTEPS * KP)        g_wsum[idx]  = 0.f;
        if (idx < KP)                 g_conf[idx]  = 0.f;
        if (idx == 0)                { g_bar = 0u; g_cdone = 0u; }
        if (idx < KP * C)             out[idx]     = proto[idx];
    }
}

// ================= K1a: wmean via WMMA bf16 (192 blocks, 86 KB smem) =================
#define SOFT_LD 40
#define K1A_SMEM 86016
__global__ void __launch_bounds__(256) k1a_kernel(const float* __restrict__ qd) {
    extern __shared__ char smraw[];
    __nv_bfloat16 (*s_soft)[SOFT_LD] = (__nv_bfloat16(*)[SOFT_LD])smraw;
    float (*s_out)[C] = (float(*)[C])(smraw + 256 * SOFT_LD * 2);

    const int step  = blockIdx.x >> 6;
    const int qbase = (blockIdx.x & 63) * 256;
    const int tid   = threadIdx.x;
    const int wid   = tid >> 5;

    {
        const float inv_t = 1.0f / (float)(step + 1);
        const float* row = qd + (size_t)(qbase + tid) * KP;
        float v[KP];
        float m = -1e30f;
#pragma unroll
        for (int i = 0; i < KP; i++) { v[i] = -row[i] * inv_t; m = fmaxf(m, v[i]); }
        float s = 0.f;
#pragma unroll
        for (int i = 0; i < KP; i++) { v[i] = __expf(v[i] - m); s += v[i]; }
        const float inv = 1.0f / s;
#pragma unroll
        for (int i = 0; i < KP; i++) s_soft[tid][i] = __float2bfloat16(v[i] * inv);
    }
    __syncthreads();

    if (tid < KP) {
        float s = 0.f;
        for (int q = 0; q < 256; q++) s += __bfloat162float(s_soft[q][tid]);
        atomicAdd(&g_wsum[step * KP + tid], s);
    }

    const int n0 = wid * 64;
    wmma::fragment<wmma::accumulator, 16, 16, 16, float> acc[2][4];
#pragma unroll
    for (int mi = 0; mi < 2; mi++)
#pragma unroll
        for (int ni = 0; ni < 4; ni++) wmma::fill_fragment(acc[mi][ni], 0.f);

    for (int kq = 0; kq < 256; kq += 16) {
        wmma::fragment<wmma::matrix_a, 16, 16, 16, __nv_bfloat16, wmma::col_major> af[2];
        wmma::fragment<wmma::matrix_b, 16, 16, 16, __nv_bfloat16, wmma::row_major> bf[4];
#pragma unroll
        for (int mi = 0; mi < 2; mi++)
            wmma::load_matrix_sync(af[mi], &s_soft[kq][mi * 16], SOFT_LD);
#pragma unroll
        for (int ni = 0; ni < 4; ni++)
            wmma::load_matrix_sync(bf[ni], g_qf16 + (size_t)(qbase + kq) * C + n0 + ni * 16, C);
#pragma unroll
        for (int mi = 0; mi < 2; mi++)
#pragma unroll
            for (int ni = 0; ni < 4; ni++)
                wmma::mma_sync(acc[mi][ni], af[mi], bf[ni], acc[mi][ni]);
    }

#pragma unroll
    for (int mi = 0; mi < 2; mi++)
#pragma unroll
        for (int ni = 0; ni < 4; ni++)
            wmma::store_matrix_sync(&s_out[mi * 16][n0 + ni * 16], acc[mi][ni], C,
                                    wmma::mem_row_major);
    __syncthreads();

    float* base = g_wmean + (size_t)step * KP * C;
    const float* src = &s_out[0][0];
#pragma unroll
    for (int i = 0; i < 64; i++) {
        int idx = tid + 256 * i;
        atomicAdd(base + idx, src[idx]);
    }
}

// ================= K1b: hq (blocks 0..511, 1 tile each) + hp (512..575) ================
#define HA_LD 72
#define HB_LD 72
#define STG_LD 66
#define K1B_SMEM 36864

__device__ __forceinline__ void hq_role(char* smraw, int t) {
    __nv_bfloat16 (*As)[HA_LD] = (__nv_bfloat16(*)[HA_LD])smraw;
    __nv_bfloat16 (*Bs)[HB_LD] = (__nv_bfloat16(*)[HB_LD])(smraw + 128 * HA_LD * 2);
    float (*stg)[STG_LD] = (float(*)[STG_LD])smraw;   // union: reused after K-loop
    const int tid = threadIdx.x;
    const int wid = tid >> 5;
    const int wm = wid >> 1;
    const int wn = wid & 1;
    const int m0 = (t & 127) * 128;
    const int n0 = (t >> 7) * 64;

    wmma::fragment<wmma::accumulator, 16, 16, 16, float> acc[2][2];
#pragma unroll
    for (int mi = 0; mi < 2; mi++)
#pragma unroll
        for (int ni = 0; ni < 2; ni++) wmma::fill_fragment(acc[mi][ni], 0.f);

    for (int kk = 0; kk < C; kk += 64) {
        __syncthreads();
#pragma unroll
        for (int i = 0; i < 4; i++) {
            int f = tid + 256 * i; int row = f >> 3; int c8 = f & 7;
            *(uint4*)&As[row][c8 * 8] =
                *(const uint4*)(g_qf16 + (size_t)(m0 + row) * C + kk + c8 * 8);
        }
#pragma unroll
        for (int i = 0; i < 2; i++) {
            int f = tid + 256 * i; int row = f >> 3; int c8 = f & 7;
            *(uint4*)&Bs[row][c8 * 8] =
                *(const uint4*)(g_wq16 + (size_t)(kk + row) * HCONF + n0 + c8 * 8);
        }
        __syncthreads();

#pragma unroll
        for (int s = 0; s < 4; s++) {
            wmma::fragment<wmma::matrix_a, 16, 16, 16, __nv_bfloat16, wmma::row_major> af[2];
            wmma::fragment<wmma::matrix_b, 16, 16, 16, __nv_bfloat16, wmma::row_major> bf[2];
#pragma unroll
            for (int mi = 0; mi < 2; mi++)
                wmma::load_matrix_sync(af[mi], &As[wm * 32 + mi * 16][s * 16], HA_LD);
#pragma unroll
            for (int ni = 0; ni < 2; ni++)
                wmma::load_matrix_sync(bf[ni], &Bs[s * 16][wn * 32 + ni * 16], HB_LD);
#pragma unroll
            for (int mi = 0; mi < 2; mi++)
#pragma unroll
                for (int ni = 0; ni < 2; ni++)
                    wmma::mma_sync(acc[mi][ni], af[mi], bf[ni], acc[mi][ni]);
        }
    }
    __syncthreads();   // K-loop done; safe to reuse As/Bs space for f32 staging
#pragma unroll
    for (int mi = 0; mi < 2; mi++)
#pragma unroll
        for (int ni = 0; ni < 2; ni++)
            wmma::store_matrix_sync(&stg[wm * 32 + mi * 16][wn * 32 + ni * 16],
                                    acc[mi][ni], STG_LD, wmma::mem_row_major);
    __syncthreads();
    // pack 128x64 f32 -> bf16 gmem
#pragma unroll
    for (int i = 0; i < 8; i++) {
        int f = tid + 256 * i;           // 0..2047, 4 f32 each
        int row = f >> 4; int c4 = (f & 15) * 4;
        float4 v = make_float4(stg[row][c4], stg[row][c4 + 1], stg[row][c4 + 2], stg[row][c4 + 3]);
        __nv_bfloat162 p0 = __floats2bfloat162_rn(v.x, v.y);
        __nv_bfloat162 p1 = __floats2bfloat162_rn(v.z, v.w);
        uint2 o; o.x = *(uint32_t*)&p0; o.y = *(uint32_t*)&p1;
        *(uint2*)(g_hq16 + (size_t)(m0 + row) * HCONF + n0 + c4) = o;
    }
}

__device__ __forceinline__ void hp_role(const float* __restrict__ proto,
                                        const float* __restrict__ Wc1, char* smraw, int b) {
    float (*a_s)[KP] = (float(*)[KP])smraw;
    float (*red)[KP][64] = (float(*)[KP][64])(smraw + 4096);
    const int tid = threadIdx.x;
    const int n  = tid & 63;
    const int kp = tid >> 6;
    const int ng = (b & 3) * 64 + n;
    const int cbase = (b >> 2) * 32;

#pragma unroll
    for (int r = 0; r < 4; r++) {
        int idx = tid + 256 * r;
        int ii = idx >> 5, k = idx & 31;
        a_s[ii][k] = proto[k * C + cbase + ii];
    }
    __syncthreads();

    float acc[KP];
#pragma unroll
    for (int k = 0; k < KP; k++) acc[k] = 0.f;

    const float* wptr = Wc1 + (size_t)(cbase + kp * 8) * HCONF + ng;
    float wv[8];
#pragma unroll
    for (int ii = 0; ii < 8; ii++) wv[ii] = wptr[(size_t)ii * HCONF];
#pragma unroll
    for (int ii = 0; ii < 8; ii++) {
        const float w = wv[ii];
        const float4* av = (const float4*)&a_s[kp * 8 + ii][0];
#pragma unroll
        for (int k4 = 0; k4 < 8; k4++) {
            float4 a4 = av[k4];
            acc[k4 * 4 + 0] = fmaf(a4.x, w, acc[k4 * 4 + 0]);
            acc[k4 * 4 + 1] = fmaf(a4.y, w, acc[k4 * 4 + 1]);
            acc[k4 * 4 + 2] = fmaf(a4.z, w, acc[k4 * 4 + 2]);
            acc[k4 * 4 + 3] = fmaf(a4.w, w, acc[k4 * 4 + 3]);
        }
    }
#pragma unroll
    for (int k = 0; k < KP; k++) red[kp][k][n] = acc[k];
    __syncthreads();
    if (tid < 64) {
#pragma unroll
        for (int k = 0; k < KP; k++) {
            float s = red[0][k][n] + red[1][k][n] + red[2][k][n] + red[3][k][n];
            atomicAdd(&g_hp[k * HCONF + ng], s);
        }
    }
}

__global__ void __launch_bounds__(256) k1b_kernel(const float* __restrict__ proto,
                                                  const float* __restrict__ Wc1) {
    extern __shared__ char dsm[];
    const int bid = blockIdx.x;
    if (bid < 512) hq_role(dsm, bid);
    else           hp_role(proto, Wc1, dsm, bid - 512);
}

// ================= K2: mlp (blocks 0..127) + conf (128..287) =================
__device__ __forceinline__ void grid_sync_at(unsigned want) {
    __threadfence();
    __syncthreads();
    if (threadIdx.x == 0) {
        atomicAdd(&g_bar, 1u);
        while (*(volatile unsigned*)&g_bar < want) __nanosleep(32);
    }
    __syncthreads();
}

__device__ __forceinline__ void mlp_role(float* __restrict__ refined,
        const float* __restrict__ W1, const float* __restrict__ W2,
        const float* __restrict__ b1, const float* __restrict__ b2, char* smraw) {
    float (*a_s)[KP] = (float(*)[KP])smraw;
    float (*red)[KP][64] = (float(*)[KP][64])(smraw + 8192);
    float (*s_winv)[KP] = (float(*)[KP])(smraw + 8192 + 32768);

    const int tid = threadIdx.x;
    const int n  = tid & 63;
    const int kp = tid >> 6;
    const int bx = blockIdx.x & 7;
    const int by = blockIdx.x >> 3;

    if (tid < NSTEPS * KP)
        s_winv[tid >> 5][tid & 31] = 1.0f / fmaxf(g_wsum[tid], 1e-6f);

    unsigned want = MLPB;

    for (int step = 0; step < NSTEPS; step++) {
        {
            const int ng = bx * 64 + n;
            const int kbase = by * 64;
            __syncthreads();
#pragma unroll
            for (int r = 0; r < 8; r++) {
                int idx = tid + 256 * r;
                int ii = idx >> 5, k = idx & 31;
                int i = kbase + ii;
                a_s[ii][k] = (i < C)
                    ? __ldcg(&refined[k * C + i])
                    : g_wmean[(size_t)(step * KP + k) * C + (i - C)] * s_winv[step][k];
            }
            __syncthreads();

            float acc[KP];
#pragma unroll
            for (int k = 0; k < KP; k++) acc[k] = 0.f;

            const float* wptr = W1 + (size_t)(kbase + kp * 16) * HREF + ng;
            float wv[16];
#pragma unroll
            for (int ii = 0; ii < 16; ii++) wv[ii] = wptr[(size_t)ii * HREF];
#pragma unroll
            for (int ii = 0; ii < 16; ii++) {
                const float w = wv[ii];
                const float4* av = (const float4*)&a_s[kp * 16 + ii][0];
#pragma unroll
                for (int k4 = 0; k4 < 8; k4++) {
                    float4 a4 = av[k4];
                    acc[k4 * 4 + 0] = fmaf(a4.x, w, acc[k4 * 4 + 0]);
                    acc[k4 * 4 + 1] = fmaf(a4.y, w, acc[k4 * 4 + 1]);
                    acc[k4 * 4 + 2] = fmaf(a4.z, w, acc[k4 * 4 + 2]);
                    acc[k4 * 4 + 3] = fmaf(a4.w, w, acc[k4 * 4 + 3]);
                }
            }
#pragma unroll
            for (int k = 0; k < KP; k++) red[kp][k][n] = acc[k];
            __syncthreads();
            if (tid < 64) {
#pragma unroll
                for (int k = 0; k < KP; k++) {
                    float s = red[0][k][n] + red[1][k][n] + red[2][k][n] + red[3][k][n];
                    atomicAdd(&g_h[(size_t)(step * KP + k) * HREF + ng], s);
                }
            }
        }
        grid_sync_at(want); want += MLPB;

        {
            const int cg = bx * 64 + n;
            const int jbase = by * 32;
#pragma unroll
            for (int r = 0; r < 4; r++) {
                int idx = tid + 256 * r;
                int ii = idx >> 5, k = idx & 31;
                int j = jbase + ii;
                a_s[ii][k] = fmaxf(__ldcg(&g_h[(size_t)(step * KP + k) * HREF + j]) + b1[j], 0.f);
            }
            __syncthreads();

            float acc[KP];
#pragma unroll
            for (int k = 0; k < KP; k++) acc[k] = 0.f;

            const float* wptr = W2 + (size_t)(jbase + kp * 8) * C + cg;
            float wv[8];
#pragma unroll
            for (int ii = 0; ii < 8; ii++) wv[ii] = wptr[(size_t)ii * C];
#pragma unroll
            for (int ii = 0; ii < 8; ii++) {
                const float w = wv[ii];
                const float4* av = (const float4*)&a_s[kp * 8 + ii][0];
#pragma unroll
                for (int k4 = 0; k4 < 8; k4++) {
                    float4 a4 = av[k4];
                    acc[k4 * 4 + 0] = fmaf(a4.x, w, acc[k4 * 4 + 0]);
                    acc[k4 * 4 + 1] = fmaf(a4.y, w, acc[k4 * 4 + 1]);
                    acc[k4 * 4 + 2] = fmaf(a4.z, w, acc[k4 * 4 + 2]);
                    acc[k4 * 4 + 3] = fmaf(a4.w, w, acc[k4 * 4 + 3]);
                }
            }
#pragma unroll
            for (int k = 0; k < KP; k++) red[kp][k][n] = acc[k];
            __syncthreads();
            if (tid < 64) {
                const float b2v = (by == 0) ? b2[cg] : 0.f;
#pragma unroll
                for (int k = 0; k < KP; k++) {
                    float s = red[0][k][n] + red[1][k][n] + red[2][k][n] + red[3][k][n];
                    atomicAdd(&refined[k * C + cg], 0.1f * (s + b2v));
                }
            }
        }
        if (step < NSTEPS - 1) { grid_sync_at(want); want += MLPB; }
    }
}

// ---- conf: lane = k, serial f32 relu-dot, no shuffle chains ----
// smem layout: s_hp f32[32][257] @0 (32896) | s_w f32[256] @32896 (1024)
//              a_buf bf16[8][4*256] @33920 (16384) | s_part f32[8][32] @50304 (1024)
//              s_last @51328
__device__ __forceinline__ void conf_role(const float* __restrict__ Wc2,
        const float* __restrict__ bc1, const float* __restrict__ bc2,
        float* __restrict__ out, char* smraw, int cb) {
    float (*s_hp)[257] = (float(*)[257])smraw;
    float* s_w = (float*)(smraw + 32896);
    __nv_bfloat16 (*a_buf)[4 * HCONF] = (__nv_bfloat16(*)[4 * HCONF])(smraw + 33920);
    float (*s_part)[KP] = (float(*)[KP])(smraw + 50304);
    unsigned* s_last = (unsigned*)(smraw + 51328);

    const int tid  = threadIdx.x;
    const int lane = tid & 31;
    const int warp = tid >> 5;

    // hp'[k][j] = g_hp[k][j] + bc1[j]
#pragma unroll
    for (int r = 0; r < 32; r++) {
        int idx = tid + 256 * r;          // 0..8191
        int k = idx >> 8, j = idx & 255;
        s_hp[k][j] = g_hp[idx] + bc1[j];
    }
    s_w[tid] = Wc2[tid];
    const float bc2v = bc2[0];
    __syncthreads();

    float conf_acc = 0.f;
    const int QB = 4;
    const int qstride = CONFB * 8 * QB;    // 5120
    __nv_bfloat16* abuf = a_buf[warp];

    for (int q0 = (cb * 8 + warp) * QB; q0 < NQ; q0 += qstride) {
        // stage 4 hq rows (bf16): each lane one uint4 per row
#pragma unroll
        for (int qq = 0; qq < QB; qq++)
            *(uint4*)&abuf[qq * HCONF + lane * 8] =
                *(const uint4*)(g_hq16 + (size_t)(q0 + qq) * HCONF + lane * 8);
        __syncwarp();

        float s0 = 0.f, s1 = 0.f, s2 = 0.f, s3 = 0.f;
#pragma unroll 8
        for (int jg = 0; jg < 64; jg++) {
            const int j = jg * 4;
            const float hp0 = s_hp[lane][j],     hp1 = s_hp[lane][j + 1];
            const float hp2 = s_hp[lane][j + 2], hp3 = s_hp[lane][j + 3];
            const float w0 = s_w[j],     w1 = s_w[j + 1];
            const float w2 = s_w[j + 2], w3 = s_w[j + 3];
#pragma unroll
            for (int qq = 0; qq < QB; qq++) {
                uint2 araw = *(const uint2*)&abuf[qq * HCONF + j];
                __nv_bfloat162 a01 = *(__nv_bfloat162*)&araw.x;
                __nv_bfloat162 a23 = *(__nv_bfloat162*)&araw.y;
                float2 f01 = __bfloat1622float2(a01);
                float2 f23 = __bfloat1622float2(a23);
                float t0 = fmaxf(hp0 + f01.x, 0.f);
                float t1 = fmaxf(hp1 + f01.y, 0.f);
                float t2 = fmaxf(hp2 + f23.x, 0.f);
                float t3 = fmaxf(hp3 + f23.y, 0.f);
                float acc = fmaf(t0, w0, fmaf(t1, w1, fmaf(t2, w2, t3 * w3)));
                if (qq == 0) s0 += acc;
                else if (qq == 1) s1 += acc;
                else if (qq == 2) s2 += acc;
                else s3 += acc;
            }
        }
        conf_acc += 1.0f / (1.0f + __expf(-(s0 + bc2v)));
        conf_acc += 1.0f / (1.0f + __expf(-(s1 + bc2v)));
        conf_acc += 1.0f / (1.0f + __expf(-(s2 + bc2v)));
        conf_acc += 1.0f / (1.0f + __expf(-(s3 + bc2v)));
    }

    s_part[warp][lane] = conf_acc;
    __syncthreads();
    if (tid < KP) {
        float t = 0.f;
#pragma unroll
        for (int w = 0; w < 8; w++) t += s_part[w][tid];
        atomicAdd(&g_conf[tid], t);
    }
    __threadfence();
    __syncthreads();
    if (tid == 0) *s_last = atomicAdd(&g_cdone, 1u);
    __syncthreads();
    if (*s_last == CONFB - 1) {
        if (tid < KP)
            out[KP * C + tid] = *((volatile float*)&g_conf[tid]) * (1.0f / (float)NQ);
    }
}

#define K2_SMEM 51456
__global__ void __launch_bounds__(256) k2_kernel(float* __restrict__ out,
        const float* __restrict__ W1, const float* __restrict__ W2,
        const float* __restrict__ b1, const float* __restrict__ b2,
        const float* __restrict__ Wc2, const float* __restrict__ bc1,
        const float* __restrict__ bc2) {
    extern __shared__ char dsm[];
    const int bid = blockIdx.x;
    if (bid < MLPB) mlp_role(out, W1, W2, b1, b2, dsm);
    else            conf_role(Wc2, bc1, bc2, out, dsm, bid - MLPB);
}

// ---------------- launch ----------------
extern "C" void kernel_launch(void* const* d_in, const int* in_sizes, int n_in,
                              void* d_out, int out_size) {
    const float* proto = (const float*)d_in[0];
    const float* qf    = (const float*)d_in[1];
    const float* qd    = (const float*)d_in[2];
    const float* W1    = (const float*)d_in[3];
    const float* b1    = (const float*)d_in[4];
    const float* W2    = (const float*)d_in[5];
    const float* b2    = (const float*)d_in[6];
    const float* Wc1   = (const float*)d_in[7];
    const float* bc1   = (const float*)d_in[8];
    const float* Wc2   = (const float*)d_in[9];
    const float* bc2   = (const float*)d_in[10];
    float* out = (float*)d_out;

    static int smem_set = 0;
    if (!smem_set) {
        cudaFuncSetAttribute(k1a_kernel, cudaFuncAttributeMaxDynamicSharedMemorySize, K1A_SMEM);
        cudaFuncSetAttribute(k1b_kernel, cudaFuncAttributeMaxDynamicSharedMemorySize, K1B_SMEM);
        cudaFuncSetAttribute(k2_kernel,  cudaFuncAttributeMaxDynamicSharedMemorySize, K2_SMEM);
        smem_set = 1;
    }

    k0_kernel<<<4352, 256>>>(proto, qf, Wc1, out);
    k1a_kernel<<<192, 256, K1A_SMEM>>>(qd);
    k1b_kernel<<<576, 256, K1B_SMEM>>>(proto, Wc1);
    k2_kernel<<<MLPB + CONFB, 256, K2_SMEM>>>(out, W1, W2, b1, b2, Wc2, bc1, bc2);
}

// round 12
// speedup vs baseline: 1.3910x; 1.0403x over previous
#include <cuda_runtime.h>
#include <cuda_bf16.h>
#include <mma.h>
#include <cstdint>

using namespace nvcuda;

#define NQ    16384
#define KP    32
#define C     512
#define HREF  512
#define HCONF 256
#define NSTEPS 3

#define MLPB  128      // mlp role blocks (grid-barrier cohort)
#define CONFB 160      // conf role blocks

// ---------------- scratch ----------------
__device__ float g_wmean[NSTEPS * KP * C];
__device__ float g_wsum [NSTEPS * KP];
__device__ float g_h    [NSTEPS * KP * HREF];
__device__ float g_hp   [KP * HCONF];
__device__ __nv_bfloat16 g_hq16[NQ * HCONF];          // 8 MB
__device__ float g_conf [KP];
__device__ __nv_bfloat16 g_qf16[NQ * C];              // 16 MB
__device__ __nv_bfloat16 g_wq16[C * HCONF];           // 256 KB
__device__ unsigned g_bar;
__device__ unsigned g_cdone;

// ================= K0: cvt (blocks 0..4159) + init (blocks 4160..4351) =================
__global__ void __launch_bounds__(256) k0_kernel(const float* __restrict__ proto,
                                                 const float* __restrict__ qf,
                                                 const float* __restrict__ Wc1,
                                                 float* __restrict__ out) {
    const int bid = blockIdx.x;
    if (bid < 4160) {
        const int idx = bid * 256 + threadIdx.x;
        const int NV_QF = NQ * C / 8;
        const float* src;
        __nv_bfloat16* dst;
        int v;
        if (idx < NV_QF) { src = qf; dst = g_qf16; v = idx; }
        else if (idx < NV_QF + C * HCONF / 8) {
            src = Wc1 + (size_t)C * HCONF; dst = g_wq16; v = idx - NV_QF;
        } else return;
        float4 a = *(const float4*)(src + (size_t)v * 8);
        float4 b = *(const float4*)(src + (size_t)v * 8 + 4);
        __nv_bfloat162 p0 = __floats2bfloat162_rn(a.x, a.y);
        __nv_bfloat162 p1 = __floats2bfloat162_rn(a.z, a.w);
        __nv_bfloat162 p2 = __floats2bfloat162_rn(b.x, b.y);
        __nv_bfloat162 p3 = __floats2bfloat162_rn(b.z, b.w);
        uint4 o;
        o.x = *(uint32_t*)&p0; o.y = *(uint32_t*)&p1;
        o.z = *(uint32_t*)&p2; o.w = *(uint32_t*)&p3;
        *(uint4*)(dst + (size_t)v * 8) = o;
    } else {
        const int idx = (bid - 4160) * 256 + threadIdx.x;
        if (idx < NSTEPS * KP * C)    g_wmean[idx] = 0.f;
        if (idx < NSTEPS * KP * HREF) g_h[idx]     = 0.f;
        if (idx < KP * HCONF)         g_hp[idx]    = 0.f;
        if (idx < NSTEPS * KP)        g_wsum[idx]  = 0.f;
        if (idx < KP)                 g_conf[idx]  = 0.f;
        if (idx == 0)                { g_bar = 0u; g_cdone = 0u; }
        if (idx < KP * C)             out[idx]     = proto[idx];
    }
}

// ================= K1a: wmean via WMMA bf16, n-halved (384 blocks, 53 KB smem) ==========
#define SOFT_LD 40
#define K1A_SMEM (256 * SOFT_LD * 2 + KP * 256 * 4)   // 20480 + 32768 = 53248
__global__ void __launch_bounds__(256) k1a_kernel(const float* __restrict__ qd) {
    extern __shared__ char smraw[];
    __nv_bfloat16 (*s_soft)[SOFT_LD] = (__nv_bfloat16(*)[SOFT_LD])smraw;
    float (*s_out)[256] = (float(*)[256])(smraw + 256 * SOFT_LD * 2);

    const int step  = blockIdx.x / 128;
    const int sub   = blockIdx.x % 128;
    const int qbase = (sub >> 1) * 256;
    const int nh    = (sub & 1) * 256;
    const int tid   = threadIdx.x;
    const int wid   = tid >> 5;

    {
        const float inv_t = 1.0f / (float)(step + 1);
        const float* row = qd + (size_t)(qbase + tid) * KP;
        float v[KP];
        float m = -1e30f;
#pragma unroll
        for (int i = 0; i < KP; i++) { v[i] = -row[i] * inv_t; m = fmaxf(m, v[i]); }
        float s = 0.f;
#pragma unroll
        for (int i = 0; i < KP; i++) { v[i] = __expf(v[i] - m); s += v[i]; }
        const float inv = 1.0f / s;
#pragma unroll
        for (int i = 0; i < KP; i++) s_soft[tid][i] = __float2bfloat16(v[i] * inv);
    }
    __syncthreads();

    if (nh == 0 && tid < KP) {
        float s = 0.f;
        for (int q = 0; q < 256; q++) s += __bfloat162float(s_soft[q][tid]);
        atomicAdd(&g_wsum[step * KP + tid], s);
    }

    const int n0 = nh + wid * 32;        // global col base for this warp
    wmma::fragment<wmma::accumulator, 16, 16, 16, float> acc[2][2];
#pragma unroll
    for (int mi = 0; mi < 2; mi++)
#pragma unroll
        for (int ni = 0; ni < 2; ni++) wmma::fill_fragment(acc[mi][ni], 0.f);

    for (int kq = 0; kq < 256; kq += 16) {
        wmma::fragment<wmma::matrix_a, 16, 16, 16, __nv_bfloat16, wmma::col_major> af[2];
        wmma::fragment<wmma::matrix_b, 16, 16, 16, __nv_bfloat16, wmma::row_major> bf[2];
#pragma unroll
        for (int mi = 0; mi < 2; mi++)
            wmma::load_matrix_sync(af[mi], &s_soft[kq][mi * 16], SOFT_LD);
#pragma unroll
        for (int ni = 0; ni < 2; ni++)
            wmma::load_matrix_sync(bf[ni], g_qf16 + (size_t)(qbase + kq) * C + n0 + ni * 16, C);
#pragma unroll
        for (int mi = 0; mi < 2; mi++)
#pragma unroll
            for (int ni = 0; ni < 2; ni++)
                wmma::mma_sync(acc[mi][ni], af[mi], bf[ni], acc[mi][ni]);
    }

#pragma unroll
    for (int mi = 0; mi < 2; mi++)
#pragma unroll
        for (int ni = 0; ni < 2; ni++)
            wmma::store_matrix_sync(&s_out[mi * 16][wid * 32 + ni * 16], acc[mi][ni], 256,
                                    wmma::mem_row_major);
    __syncthreads();

    float* base = g_wmean + (size_t)step * KP * C + nh;
    const float* src = &s_out[0][0];
#pragma unroll
    for (int i = 0; i < 32; i++) {
        int idx = tid + 256 * i;          // 0..8191 == m*256 + c
        atomicAdd(base + (idx >> 8) * C + (idx & 255), src[idx]);
    }
}

// ================= K1b: hq (blocks 0..511, 1 tile each) + hp (512..575) ================
#define HA_LD 72
#define HB_LD 72
#define STG_LD 66
#define K1B_SMEM 36864

__device__ __forceinline__ void hq_role(char* smraw, int t) {
    __nv_bfloat16 (*As)[HA_LD] = (__nv_bfloat16(*)[HA_LD])smraw;
    __nv_bfloat16 (*Bs)[HB_LD] = (__nv_bfloat16(*)[HB_LD])(smraw + 128 * HA_LD * 2);
    float (*stg)[STG_LD] = (float(*)[STG_LD])smraw;   // union: reused after K-loop
    const int tid = threadIdx.x;
    const int wid = tid >> 5;
    const int wm = wid >> 1;
    const int wn = wid & 1;
    const int m0 = (t & 127) * 128;
    const int n0 = (t >> 7) * 64;

    wmma::fragment<wmma::accumulator, 16, 16, 16, float> acc[2][2];
#pragma unroll
    for (int mi = 0; mi < 2; mi++)
#pragma unroll
        for (int ni = 0; ni < 2; ni++) wmma::fill_fragment(acc[mi][ni], 0.f);

    for (int kk = 0; kk < C; kk += 64) {
        __syncthreads();
#pragma unroll
        for (int i = 0; i < 4; i++) {
            int f = tid + 256 * i; int row = f >> 3; int c8 = f & 7;
            *(uint4*)&As[row][c8 * 8] =
                *(const uint4*)(g_qf16 + (size_t)(m0 + row) * C + kk + c8 * 8);
        }
#pragma unroll
        for (int i = 0; i < 2; i++) {
            int f = tid + 256 * i; int row = f >> 3; int c8 = f & 7;
            *(uint4*)&Bs[row][c8 * 8] =
                *(const uint4*)(g_wq16 + (size_t)(kk + row) * HCONF + n0 + c8 * 8);
        }
        __syncthreads();

#pragma unroll
        for (int s = 0; s < 4; s++) {
            wmma::fragment<wmma::matrix_a, 16, 16, 16, __nv_bfloat16, wmma::row_major> af[2];
            wmma::fragment<wmma::matrix_b, 16, 16, 16, __nv_bfloat16, wmma::row_major> bf[2];
#pragma unroll
            for (int mi = 0; mi < 2; mi++)
                wmma::load_matrix_sync(af[mi], &As[wm * 32 + mi * 16][s * 16], HA_LD);
#pragma unroll
            for (int ni = 0; ni < 2; ni++)
                wmma::load_matrix_sync(bf[ni], &Bs[s * 16][wn * 32 + ni * 16], HB_LD);
#pragma unroll
            for (int mi = 0; mi < 2; mi++)
#pragma unroll
                for (int ni = 0; ni < 2; ni++)
                    wmma::mma_sync(acc[mi][ni], af[mi], bf[ni], acc[mi][ni]);
        }
    }
    __syncthreads();   // K-loop done; safe to reuse As/Bs space for f32 staging
#pragma unroll
    for (int mi = 0; mi < 2; mi++)
#pragma unroll
        for (int ni = 0; ni < 2; ni++)
            wmma::store_matrix_sync(&stg[wm * 32 + mi * 16][wn * 32 + ni * 16],
                                    acc[mi][ni], STG_LD, wmma::mem_row_major);
    __syncthreads();
    // pack 128x64 f32 -> bf16 gmem
#pragma unroll
    for (int i = 0; i < 8; i++) {
        int f = tid + 256 * i;           // 0..2047, 4 f32 each
        int row = f >> 4; int c4 = (f & 15) * 4;
        float4 v = make_float4(stg[row][c4], stg[row][c4 + 1], stg[row][c4 + 2], stg[row][c4 + 3]);
        __nv_bfloat162 p0 = __floats2bfloat162_rn(v.x, v.y);
        __nv_bfloat162 p1 = __floats2bfloat162_rn(v.z, v.w);
        uint2 o; o.x = *(uint32_t*)&p0; o.y = *(uint32_t*)&p1;
        *(uint2*)(g_hq16 + (size_t)(m0 + row) * HCONF + n0 + c4) = o;
    }
}

__device__ __forceinline__ void hp_role(const float* __restrict__ proto,
                                        const float* __restrict__ Wc1, char* smraw, int b) {
    float (*a_s)[KP] = (float(*)[KP])smraw;
    float (*red)[KP][64] = (float(*)[KP][64])(smraw + 4096);
    const int tid = threadIdx.x;
    const int n  = tid & 63;
    const int kp = tid >> 6;
    const int ng = (b & 3) * 64 + n;
    const int cbase = (b >> 2) * 32;

#pragma unroll
    for (int r = 0; r < 4; r++) {
        int idx = tid + 256 * r;
        int ii = idx >> 5, k = idx & 31;
        a_s[ii][k] = proto[k * C + cbase + ii];
    }
    __syncthreads();

    float acc[KP];
#pragma unroll
    for (int k = 0; k < KP; k++) acc[k] = 0.f;

    const float* wptr = Wc1 + (size_t)(cbase + kp * 8) * HCONF + ng;
    float wv[8];
#pragma unroll
    for (int ii = 0; ii < 8; ii++) wv[ii] = wptr[(size_t)ii * HCONF];
#pragma unroll
    for (int ii = 0; ii < 8; ii++) {
        const float w = wv[ii];
        const float4* av = (const float4*)&a_s[kp * 8 + ii][0];
#pragma unroll
        for (int k4 = 0; k4 < 8; k4++) {
            float4 a4 = av[k4];
            acc[k4 * 4 + 0] = fmaf(a4.x, w, acc[k4 * 4 + 0]);
            acc[k4 * 4 + 1] = fmaf(a4.y, w, acc[k4 * 4 + 1]);
            acc[k4 * 4 + 2] = fmaf(a4.z, w, acc[k4 * 4 + 2]);
            acc[k4 * 4 + 3] = fmaf(a4.w, w, acc[k4 * 4 + 3]);
        }
    }
#pragma unroll
    for (int k = 0; k < KP; k++) red[kp][k][n] = acc[k];
    __syncthreads();
    if (tid < 64) {
#pragma unroll
        for (int k = 0; k < KP; k++) {
            float s = red[0][k][n] + red[1][k][n] + red[2][k][n] + red[3][k][n];
            atomicAdd(&g_hp[k * HCONF + ng], s);
        }
    }
}

__global__ void __launch_bounds__(256) k1b_kernel(const float* __restrict__ proto,
                                                  const float* __restrict__ Wc1) {
    extern __shared__ char dsm[];
    const int bid = blockIdx.x;
    if (bid < 512) hq_role(dsm, bid);
    else           hp_role(proto, Wc1, dsm, bid - 512);
}

// ================= K2: mlp (blocks 0..127) + conf (128..287) =================
__device__ __forceinline__ void grid_sync_at(unsigned want) {
    __threadfence();
    __syncthreads();
    if (threadIdx.x == 0) {
        atomicAdd(&g_bar, 1u);
        while (*(volatile unsigned*)&g_bar < want) __nanosleep(32);
    }
    __syncthreads();
}

__device__ __forceinline__ void mlp_role(float* __restrict__ refined,
        const float* __restrict__ W1, const float* __restrict__ W2,
        const float* __restrict__ b1, const float* __restrict__ b2, char* smraw) {
    float (*a_s)[KP] = (float(*)[KP])smraw;
    float (*red)[KP][64] = (float(*)[KP][64])(smraw + 8192);
    float (*s_winv)[KP] = (float(*)[KP])(smraw + 8192 + 32768);

    const int tid = threadIdx.x;
    const int n  = tid & 63;
    const int kp = tid >> 6;
    const int bx = blockIdx.x & 7;
    const int by = blockIdx.x >> 3;

    if (tid < NSTEPS * KP)
        s_winv[tid >> 5][tid & 31] = 1.0f / fmaxf(g_wsum[tid], 1e-6f);

    unsigned want = MLPB;

    for (int step = 0; step < NSTEPS; step++) {
        {
            const int ng = bx * 64 + n;
            const int kbase = by * 64;
            __syncthreads();
#pragma unroll
            for (int r = 0; r < 8; r++) {
                int idx = tid + 256 * r;
                int ii = idx >> 5, k = idx & 31;
                int i = kbase + ii;
                a_s[ii][k] = (i < C)
                    ? __ldcg(&refined[k * C + i])
                    : g_wmean[(size_t)(step * KP + k) * C + (i - C)] * s_winv[step][k];
            }
            __syncthreads();

            float acc[KP];
#pragma unroll
            for (int k = 0; k < KP; k++) acc[k] = 0.f;

            const float* wptr = W1 + (size_t)(kbase + kp * 16) * HREF + ng;
            float wv[16];
#pragma unroll
            for (int ii = 0; ii < 16; ii++) wv[ii] = wptr[(size_t)ii * HREF];
#pragma unroll
            for (int ii = 0; ii < 16; ii++) {
                const float w = wv[ii];
                const float4* av = (const float4*)&a_s[kp * 16 + ii][0];
#pragma unroll
                for (int k4 = 0; k4 < 8; k4++) {
                    float4 a4 = av[k4];
                    acc[k4 * 4 + 0] = fmaf(a4.x, w, acc[k4 * 4 + 0]);
                    acc[k4 * 4 + 1] = fmaf(a4.y, w, acc[k4 * 4 + 1]);
                    acc[k4 * 4 + 2] = fmaf(a4.z, w, acc[k4 * 4 + 2]);
                    acc[k4 * 4 + 3] = fmaf(a4.w, w, acc[k4 * 4 + 3]);
                }
            }
#pragma unroll
            for (int k = 0; k < KP; k++) red[kp][k][n] = acc[k];
            __syncthreads();
            if (tid < 64) {
#pragma unroll
                for (int k = 0; k < KP; k++) {
                    float s = red[0][k][n] + red[1][k][n] + red[2][k][n] + red[3][k][n];
                    atomicAdd(&g_h[(size_t)(step * KP + k) * HREF + ng], s);
                }
            }
        }
        grid_sync_at(want); want += MLPB;

        {
            const int cg = bx * 64 + n;
            const int jbase = by * 32;
#pragma unroll
            for (int r = 0; r < 4; r++) {
                int idx = tid + 256 * r;
                int ii = idx >> 5, k = idx & 31;
                int j = jbase + ii;
                a_s[ii][k] = fmaxf(__ldcg(&g_h[(size_t)(step * KP + k) * HREF + j]) + b1[j], 0.f);
            }
            __syncthreads();

            float acc[KP];
#pragma unroll
            for (int k = 0; k < KP; k++) acc[k] = 0.f;

            const float* wptr = W2 + (size_t)(jbase + kp * 8) * C + cg;
            float wv[8];
#pragma unroll
            for (int ii = 0; ii < 8; ii++) wv[ii] = wptr[(size_t)ii * C];
#pragma unroll
            for (int ii = 0; ii < 8; ii++) {
                const float w = wv[ii];
                const float4* av = (const float4*)&a_s[kp * 8 + ii][0];
#pragma unroll
                for (int k4 = 0; k4 < 8; k4++) {
                    float4 a4 = av[k4];
                    acc[k4 * 4 + 0] = fmaf(a4.x, w, acc[k4 * 4 + 0]);
                    acc[k4 * 4 + 1] = fmaf(a4.y, w, acc[k4 * 4 + 1]);
                    acc[k4 * 4 + 2] = fmaf(a4.z, w, acc[k4 * 4 + 2]);
                    acc[k4 * 4 + 3] = fmaf(a4.w, w, acc[k4 * 4 + 3]);
                }
            }
#pragma unroll
            for (int k = 0; k < KP; k++) red[kp][k][n] = acc[k];
            __syncthreads();
            if (tid < 64) {
                const float b2v = (by == 0) ? b2[cg] : 0.f;
#pragma unroll
                for (int k = 0; k < KP; k++) {
                    float s = red[0][k][n] + red[1][k][n] + red[2][k][n] + red[3][k][n];
                    atomicAdd(&refined[k * C + cg], 0.1f * (s + b2v));
                }
            }
        }
        if (step < NSTEPS - 1) { grid_sync_at(want); want += MLPB; }
    }
}

// ---- conf v3: lane = k, relu via free |x| modifier (all-fma inner loop), f32 staging ----
// smem: s_hp f32[32*260] @0 (33280) | s_w f32[256] @33280 (1024)
//       a_buf f32[8][1024] @34304 (32768) | s_part @67072 (1024) | s_last @68096
__device__ __forceinline__ void conf_role(const float* __restrict__ Wc2,
        const float* __restrict__ bc1, const float* __restrict__ bc2,
        float* __restrict__ out, char* smraw, int cb) {
    float* s_hp  = (float*)smraw;
    float* s_w   = (float*)(smraw + 33280);
    float* a_all = (float*)(smraw + 34304);
    float (*s_part)[KP] = (float(*)[KP])(smraw + 67072);
    unsigned* s_last = (unsigned*)(smraw + 68096);

    const int tid  = threadIdx.x;
    const int lane = tid & 31;
    const int warp = tid >> 5;

    // hp'[k][j] = g_hp[k][j] + bc1[j], row stride 260 (16B-aligned, conflict-free LDS.128)
#pragma unroll
    for (int r = 0; r < 32; r++) {
        int idx = tid + 256 * r;          // 0..8191
        int k = idx >> 8, j = idx & 255;
        s_hp[k * 260 + j] = g_hp[idx] + bc1[j];
    }
    s_w[tid] = 0.5f * Wc2[tid];           // fold the relu half-factor
    const float bc2v = bc2[0];
    __syncthreads();

    float conf_acc = 0.f;
    const int QB = 4;
    const int qstride = CONFB * 8 * QB;    // 5120
    float* abuf = a_all + warp * (QB * HCONF);
    const float* hprow = s_hp + lane * 260;

    for (int q0 = (cb * 8 + warp) * QB; q0 < NQ; q0 += qstride) {
        __syncwarp();
        // stage 4 hq rows: bf16 -> f32 once
#pragma unroll
        for (int qq = 0; qq < QB; qq++) {
            uint4 hv = *(const uint4*)(g_hq16 + (size_t)(q0 + qq) * HCONF + lane * 8);
            __nv_bfloat162 h2[4]; *(uint4*)h2 = hv;
            float2 f0 = __bfloat1622float2(h2[0]);
            float2 f1 = __bfloat1622float2(h2[1]);
            float2 f2 = __bfloat1622float2(h2[2]);
            float2 f3 = __bfloat1622float2(h2[3]);
            float* dst = abuf + qq * HCONF + lane * 8;
            *(float4*)dst       = make_float4(f0.x, f0.y, f1.x, f1.y);
            *(float4*)(dst + 4) = make_float4(f2.x, f2.y, f3.x, f3.y);
        }
        __syncwarp();

        float s0 = 0.f, s1 = 0.f, s2 = 0.f, s3 = 0.f;
#pragma unroll 8
        for (int jg = 0; jg < 64; jg++) {
            const float4 hp4 = *(const float4*)(hprow + jg * 4);
            const float4 w4  = *(const float4*)(s_w + jg * 4);
#pragma unroll
            for (int qq = 0; qq < QB; qq++) {
                float4 a4 = *(const float4*)(abuf + qq * HCONF + jg * 4);
                float x0 = hp4.x + a4.x;
                float x1 = hp4.y + a4.y;
                float x2 = hp4.z + a4.z;
                float x3 = hp4.w + a4.w;
                float acc = (x0 + fabsf(x0)) * w4.x;
                acc = fmaf(x1 + fabsf(x1), w4.y, acc);
                acc = fmaf(x2 + fabsf(x2), w4.z, acc);
                acc = fmaf(x3 + fabsf(x3), w4.w, acc);
                if (qq == 0) s0 += acc;
                else if (qq == 1) s1 += acc;
                else if (qq == 2) s2 += acc;
                else s3 += acc;
            }
        }
        conf_acc += 1.0f / (1.0f + __expf(-(s0 + bc2v)));
        conf_acc += 1.0f / (1.0f + __expf(-(s1 + bc2v)));
        conf_acc += 1.0f / (1.0f + __expf(-(s2 + bc2v)));
        conf_acc += 1.0f / (1.0f + __expf(-(s3 + bc2v)));
    }

    s_part[warp][lane] = conf_acc;
    __syncthreads();
    if (tid < KP) {
        float t = 0.f;
#pragma unroll
        for (int w = 0; w < 8; w++) t += s_part[w][tid];
        atomicAdd(&g_conf[tid], t);
    }
    __threadfence();
    __syncthreads();
    if (tid == 0) *s_last = atomicAdd(&g_cdone, 1u);
    __syncthreads();
    if (*s_last == CONFB - 1) {
        if (tid < KP)
            out[KP * C + tid] = *((volatile float*)&g_conf[tid]) * (1.0f / (float)NQ);
    }
}

#define K2_SMEM 68224
__global__ void __launch_bounds__(256) k2_kernel(float* __restrict__ out,
        const float* __restrict__ W1, const float* __restrict__ W2,
        const float* __restrict__ b1, const float* __restrict__ b2,
        const float* __restrict__ Wc2, const float* __restrict__ bc1,
        const float* __restrict__ bc2) {
    extern __shared__ char dsm[];
    const int bid = blockIdx.x;
    if (bid < MLPB) mlp_role(out, W1, W2, b1, b2, dsm);
    else            conf_role(Wc2, bc1, bc2, out, dsm, bid - MLPB);
}

// ---------------- launch ----------------
extern "C" void kernel_launch(void* const* d_in, const int* in_sizes, int n_in,
                              void* d_out, int out_size) {
    const float* proto = (const float*)d_in[0];
    const float* qf    = (const float*)d_in[1];
    const float* qd    = (const float*)d_in[2];
    const float* W1    = (const float*)d_in[3];
    const float* b1    = (const float*)d_in[4];
    const float* W2    = (const float*)d_in[5];
    const float* b2    = (const float*)d_in[6];
    const float* Wc1   = (const float*)d_in[7];
    const float* bc1   = (const float*)d_in[8];
    const float* Wc2   = (const float*)d_in[9];
    const float* bc2   = (const float*)d_in[10];
    float* out = (float*)d_out;

    static int smem_set = 0;
    if (!smem_set) {
        cudaFuncSetAttribute(k1a_kernel, cudaFuncAttributeMaxDynamicSharedMemorySize, K1A_SMEM);
        cudaFuncSetAttribute(k1b_kernel, cudaFuncAttributeMaxDynamicSharedMemorySize, K1B_SMEM);
        cudaFuncSetAttribute(k2_kernel,  cudaFuncAttributeMaxDynamicSharedMemorySize, K2_SMEM);
        smem_set = 1;
    }

    k0_kernel<<<4352, 256>>>(proto, qf, Wc1, out);
    k1a_kernel<<<384, 256, K1A_SMEM>>>(qd);
    k1b_kernel<<<576, 256, K1B_SMEM>>>(proto, Wc1);
    k2_kernel<<<MLPB + CONFB, 256, K2_SMEM>>>(out, W1, W2, b1, b2, Wc2, bc1, bc2);
}